// round 1
// baseline (speedup 1.0000x reference)
#include <cuda_runtime.h>

// Problem constants
#define BB 2
#define TT 2048
#define HH 16
#define DD 64
#define CC 1024
#define MM (BB*TT)        // 4096 rows
#define NQKV (3*CC)       // 3072

// Scratch (device globals -- no allocation allowed)
__device__ float g_qkv[MM * NQKV];      // [4096, 3072]
__device__ float g_q[BB*HH*TT*DD];      // [B,H,T,D]
__device__ float g_k[BB*HH*TT*DD];
__device__ float g_v[BB*HH*TT*DD];
__device__ float g_att[MM * CC];        // [B,T,C]

// ---------------------------------------------------------------------------
// SGEMM: C[m][n] = sum_k A[m][k] * B[n][k]   (both K-contiguous row-major)
// 64x64 block tile, BK=16, 256 threads, 4x4 per-thread micro-tile.
// ---------------------------------------------------------------------------
__global__ __launch_bounds__(256) void sgemm_nt(
    const float* __restrict__ A, const float* __restrict__ Bm,
    float* __restrict__ Cm, int M, int N, int K)
{
    __shared__ float As[16][68];  // [k][m], padded to 68 (16B-aligned, 2-way max)
    __shared__ float Bs[16][68];  // [k][n]

    const int tid = threadIdx.x;
    const int tx = tid & 15;          // n micro index
    const int ty = tid >> 4;          // m micro index
    const int m0 = blockIdx.y * 64;
    const int n0 = blockIdx.x * 64;

    // load mapping: 256 threads, each loads one float4 of A and B per k-tile
    const int lr = tid >> 2;          // row 0..63
    const int lk = (tid & 3) << 2;    // k 0,4,8,12
    const float* Ap = A  + (size_t)(m0 + lr) * K + lk;
    const float* Bp = Bm + (size_t)(n0 + lr) * K + lk;

    float acc[4][4] = {};

    for (int k0 = 0; k0 < K; k0 += 16) {
        float4 av = *(const float4*)(Ap + k0);
        float4 bv = *(const float4*)(Bp + k0);
        As[lk+0][lr] = av.x; As[lk+1][lr] = av.y;
        As[lk+2][lr] = av.z; As[lk+3][lr] = av.w;
        Bs[lk+0][lr] = bv.x; Bs[lk+1][lr] = bv.y;
        Bs[lk+2][lr] = bv.z; Bs[lk+3][lr] = bv.w;
        __syncthreads();

        #pragma unroll
        for (int k = 0; k < 16; k++) {
            float4 a4 = *(const float4*)&As[k][ty << 2];
            float4 b4 = *(const float4*)&Bs[k][tx << 2];
            float ar[4] = {a4.x, a4.y, a4.z, a4.w};
            float br[4] = {b4.x, b4.y, b4.z, b4.w};
            #pragma unroll
            for (int i = 0; i < 4; i++)
                #pragma unroll
                for (int j = 0; j < 4; j++)
                    acc[i][j] += ar[i] * br[j];
        }
        __syncthreads();
    }

    #pragma unroll
    for (int i = 0; i < 4; i++) {
        float* Cp = Cm + (size_t)(m0 + (ty << 2) + i) * N + n0 + (tx << 2);
        float4 v = {acc[i][0], acc[i][1], acc[i][2], acc[i][3]};
        *(float4*)Cp = v;
    }
}

// ---------------------------------------------------------------------------
// RoPE + scatter qkv -> q/k/v in [B,H,T,D] layout.
// One thread per (b,t,h,d<32) pair; handles d and d+32 of q,k,v.
// rotate_half(x)[d] = -x[d+32] (d<32) ; x[d-32] (d>=32)
// ---------------------------------------------------------------------------
__global__ __launch_bounds__(256) void rope_scatter(
    const float* __restrict__ cosp, const float* __restrict__ sinp)
{
    int idx = blockIdx.x * blockDim.x + threadIdx.x;
    if (idx >= BB * TT * HH * 32) return;
    int d = idx & 31;
    int h = (idx >> 5) & (HH - 1);
    int t = (idx >> 9) & (TT - 1);
    int b = idx >> 20;

    const float* row = g_qkv + (size_t)(b * TT + t) * NQKV;
    int base = h * DD + d;

    float c0 = cosp[t * DD + d],      c1 = cosp[t * DD + d + 32];
    float s0 = sinp[t * DD + d],      s1 = sinp[t * DD + d + 32];

    float q0 = row[base],            q1 = row[base + 32];
    float k0 = row[CC + base],       k1 = row[CC + base + 32];
    float v0 = row[2 * CC + base],   v1 = row[2 * CC + base + 32];

    size_t hoff = ((size_t)(b * HH + h) * TT + t) * DD + d;
    g_q[hoff]      = q0 * c0 - q1 * s0;
    g_q[hoff + 32] = q1 * c1 + q0 * s1;
    g_k[hoff]      = k0 * c0 - k1 * s0;
    g_k[hoff + 32] = k1 * c1 + k0 * s1;
    g_v[hoff]      = v0;
    g_v[hoff + 32] = v1;
}

// ---------------------------------------------------------------------------
// Causal flash attention. One thread = one query row. 128 rows per block.
// K/V staged in smem in 32-row tiles; all inner-loop smem reads broadcast.
// ---------------------------------------------------------------------------
__global__ __launch_bounds__(128) void attn_kernel(float scale)
{
    const int bh = blockIdx.y;               // 0..31  (b*H + h)
    const int q0 = blockIdx.x * 128;
    const int b = bh / HH, h = bh % HH;
    const int t = q0 + threadIdx.x;          // this thread's query row

    const float* Qp = g_q + (size_t)bh * TT * DD;
    const float* Kp = g_k + (size_t)bh * TT * DD;
    const float* Vp = g_v + (size_t)bh * TT * DD;

    __shared__ float Ks[32 * 64];
    __shared__ float Vs[32 * 64];

    float q[64], o[64];
    #pragma unroll
    for (int d = 0; d < 64; d += 4) {
        float4 v4 = *(const float4*)(Qp + (size_t)t * 64 + d);
        q[d] = v4.x; q[d+1] = v4.y; q[d+2] = v4.z; q[d+3] = v4.w;
    }
    #pragma unroll
    for (int d = 0; d < 64; d++) o[d] = 0.f;

    float m = -1e30f, l = 0.f;
    const int kend = q0 + 128;               // exclusive; causal bound for block

    for (int j0 = 0; j0 < kend; j0 += 32) {
        // cooperative load of K,V tiles: 2048 floats each, 4 float4 per thread
        #pragma unroll
        for (int i = 0; i < 4; i++) {
            int off = (i * 128 + threadIdx.x) * 4;
            *(float4*)(Ks + off) = *(const float4*)(Kp + (size_t)j0 * 64 + off);
            *(float4*)(Vs + off) = *(const float4*)(Vp + (size_t)j0 * 64 + off);
        }
        __syncthreads();

        float s[32];
        float tmax = -1e30f;
        #pragma unroll
        for (int j = 0; j < 32; j++) {
            float a0 = 0.f, a1 = 0.f, a2 = 0.f, a3 = 0.f;
            const float* kr = Ks + j * 64;
            #pragma unroll
            for (int d = 0; d < 64; d += 4) {
                a0 += q[d]   * kr[d];
                a1 += q[d+1] * kr[d+1];
                a2 += q[d+2] * kr[d+2];
                a3 += q[d+3] * kr[d+3];
            }
            float acc = ((a0 + a1) + (a2 + a3)) * scale;
            if (j0 + j > t) acc = -1e30f;    // causal mask
            s[j] = acc;
            tmax = fmaxf(tmax, acc);
        }

        float newm = fmaxf(m, tmax);
        float alpha = __expf(m - newm);
        l *= alpha;
        #pragma unroll
        for (int d = 0; d < 64; d++) o[d] *= alpha;

        #pragma unroll
        for (int j = 0; j < 32; j++) {
            float p = __expf(s[j] - newm);
            l += p;
            const float* vr = Vs + j * 64;
            #pragma unroll
            for (int d = 0; d < 64; d++) o[d] += p * vr[d];
        }
        m = newm;
        __syncthreads();
    }

    float inv = 1.f / l;
    float* dst = g_att + (size_t)(b * TT + t) * CC + h * DD;
    #pragma unroll
    for (int d = 0; d < 64; d += 4) {
        float4 v4 = {o[d]*inv, o[d+1]*inv, o[d+2]*inv, o[d+3]*inv};
        *(float4*)(dst + d) = v4;
    }
}

// ---------------------------------------------------------------------------
// Launch
// ---------------------------------------------------------------------------
extern "C" void kernel_launch(void* const* d_in, const int* in_sizes, int n_in,
                              void* d_out, int out_size)
{
    const float* x     = (const float*)d_in[0];   // [2,2048,1024]
    const float* cosp  = (const float*)d_in[1];   // [2048,64]
    const float* sinp  = (const float*)d_in[2];   // [2048,64]
    const float* w_qkv = (const float*)d_in[3];   // [3072,1024]
    const float* w_out = (const float*)d_in[4];   // [1024,1024]
    float* out = (float*)d_out;                   // [2,2048,1024]

    float *p_qkv, *p_att;
    cudaGetSymbolAddress((void**)&p_qkv, g_qkv);
    cudaGetSymbolAddress((void**)&p_att, g_att);

    // 1) qkv = x @ w_qkv^T   : M=4096, N=3072, K=1024
    {
        dim3 grid(NQKV / 64, MM / 64);
        sgemm_nt<<<grid, 256>>>(x, w_qkv, p_qkv, MM, NQKV, CC);
    }

    // 2) RoPE + scatter to [B,H,T,D]
    {
        int total = BB * TT * HH * 32;
        rope_scatter<<<(total + 255) / 256, 256>>>(cosp, sinp);
    }

    // 3) causal flash attention -> g_att [B,T,C]
    {
        dim3 grid(TT / 128, BB * HH);
        attn_kernel<<<grid, 128>>>(0.125f);   // 1/sqrt(64)
    }

    // 4) out = g_att @ w_out^T : M=4096, N=1024, K=1024
    {
        dim3 grid(CC / 64, MM / 64);
        sgemm_nt<<<grid, 256>>>(p_att, w_out, out, MM, CC, CC);
    }
}